// round 15
// baseline (speedup 1.0000x reference)
#include <cuda_runtime.h>
#include <math.h>

#define B_    128
#define NA_   32
#define N_    4096
#define E_    65536
#define T_    262144
#define EA_   128
#define EE_   128
#define DT_   64
#define NR_   64
#define NS_   16
#define NB_   3
#define LAT_  128
#define HID_  256
#define NC_   230
#define PI_F  3.14159265358979323846f

typedef unsigned long long u64;

__device__ __forceinline__ void fma2(u64& d, u64 a, u64 b) {
    asm("fma.rn.f32x2 %0, %1, %2, %0;" : "+l"(d) : "l"(a), "l"(b));
}
__device__ __forceinline__ u64 pack2(float x) {
    u64 r; asm("mov.b64 %0, {%1, %1};" : "=l"(r) : "f"(x)); return r;
}
__device__ __forceinline__ float2 unpack2(u64 v) {
    float2 r; asm("mov.b64 {%0, %1}, %2;" : "=f"(r.x), "=f"(r.y) : "l"(v)); return r;
}
__device__ __forceinline__ void red4(float* p, float4 v) {
    asm volatile("red.global.add.v4.f32 [%0], {%1, %2, %3, %4};"
                 :: "l"(p), "f"(v.x), "f"(v.y), "f"(v.z), "f"(v.w) : "memory");
}

// ---- scratch ----
__device__ float g_pos [N_*3];
__device__ float g_vec [E_*3];
__device__ float g_rbf [E_*NR_];
__device__ float g_cth [T_];
__device__ float g_h   [N_*EA_];
__device__ float g_X1  [N_*EE_];
__device__ float g_X2  [N_*EE_];
__device__ float g_m   [E_*EE_];
__device__ float g_x   [E_*DT_];
__device__ float g_segE[E_*DT_];
__device__ float g_aN  [N_*EA_];
__device__ float g_hs  [N_*EA_];
__device__ float g_ht  [N_*EA_];
__device__ float g_z   [B_*LAT_];
__device__ float g_f0  [B_*HID_];
__device__ float g_f1  [B_*HID_];

__device__ __forceinline__ float siluf(float v) {
    return v * (1.0f / (1.0f + __expf(-v)));
}

// ================= geometry =================
__global__ void k_pos(const float* __restrict__ frac,
                      const float* __restrict__ lengths,
                      const float* __restrict__ angles)
{
    int n = blockIdx.x * blockDim.x + threadIdx.x;
    if (n >= N_) return;
    int b = n / NA_;
    float a  = lengths[b*3+0], bb = lengths[b*3+1], c = lengths[b*3+2];
    float al = angles[b*3+0] * (PI_F/180.0f);
    float be = angles[b*3+1] * (PI_F/180.0f);
    float ga = angles[b*3+2] * (PI_F/180.0f);
    float ca = cosf(al), cb = cosf(be), cg = cosf(ga), sg = sinf(ga);
    float cx = cb;
    float cy = (ca - cb*cg) / sg;
    float cz = sqrtf(fmaxf(1.0f - cx*cx - cy*cy, 1e-8f));
    float f0 = frac[n*3+0], f1 = frac[n*3+1], f2 = frac[n*3+2];
    g_pos[n*3+0] = f0*a + f1*bb*cg + f2*c*cx;
    g_pos[n*3+1] =        f1*bb*sg + f2*c*cy;
    g_pos[n*3+2] =                   f2*c*cz;
}

// thread-per-edge; ONE sincosf + Chebyshev-style sine recurrence for all 64 terms.
__global__ void k_edge(const int* __restrict__ ei)
{
    int e = blockIdx.x * blockDim.x + threadIdx.x;
    if (e >= E_) return;
    int s = ei[e], dd = ei[E_ + e];
    float vx = g_pos[dd*3+0] - g_pos[s*3+0];
    float vy = g_pos[dd*3+1] - g_pos[s*3+1];
    float vz = g_pos[dd*3+2] - g_pos[s*3+2];
    g_vec[e*3+0] = vx; g_vec[e*3+1] = vy; g_vec[e*3+2] = vz;
    float d  = sqrtf(vx*vx + vy*vy + vz*vz + 1e-12f);
    float ds = d * (1.0f / 7.0f);
    float env = 0.0f;
    if (ds < 1.0f) {
        float d2 = ds*ds; float d4 = d2*d2; float d5 = d4*ds;
        env = 1.0f - 21.0f*d5 + 35.0f*d5*ds - 15.0f*d5*d2;
    }
    float coef = env * sqrtf(2.0f/7.0f) / d;
    float th = PI_F * ds;
    float s1, c1;
    sincosf(th, &s1, &c1);
    float c2 = 2.0f * c1;
    // s_n = sin(n*th):  s_{n+1} = c2*s_n - s_{n-1}
    float sp = 0.0f, sn = s1;
    float* row = &g_rbf[(size_t)e * NR_];
    #pragma unroll
    for (int q = 0; q < NR_/4; q++) {
        float4 v;
        v.x = coef * sn; { float t = c2*sn - sp; sp = sn; sn = t; }
        v.y = coef * sn; { float t = c2*sn - sp; sp = sn; sn = t; }
        v.z = coef * sn; { float t = c2*sn - sp; sp = sn; sn = t; }
        v.w = coef * sn; { float t = c2*sn - sp; sp = sn; sn = t; }
        *reinterpret_cast<float4*>(&row[q*4]) = v;
    }
}

__global__ void k_cth(const int* __restrict__ ji, const int* __restrict__ kj)
{
    int t = blockIdx.x * blockDim.x + threadIdx.x;
    if (t >= T_) return;
    int a = ji[t], b = kj[t];
    float ax = g_vec[a*3+0], ay = g_vec[a*3+1], az = g_vec[a*3+2];
    float bx = g_vec[b*3+0], by = g_vec[b*3+1], bz = g_vec[b*3+2];
    float dot = ax*bx + ay*by + az*bz;
    float n1  = sqrtf(ax*ax + ay*ay + az*az);
    float n2  = sqrtf(bx*bx + by*by + bz*bz);
    float c   = dot / (n1*n2 + 1e-9f);
    g_cth[t] = fminf(fmaxf(c, -1.0f + 1e-6f), 1.0f - 1e-6f);
}

// ================= node features =================
__global__ void k_h(const int* __restrict__ atype,
                    const float* __restrict__ noise,
                    const float* __restrict__ emb,
                    const float* __restrict__ W_hz)
{
    __shared__ float row[EA_ + 1];
    int a = blockIdx.x, c = threadIdx.x;
    int ty = atype[a];
    row[c] = emb[ty*EA_ + c];
    if (c == 0) row[EA_] = noise[a / NA_];
    __syncthreads();
    float acc = 0.0f;
    #pragma unroll 8
    for (int i = 0; i < EA_ + 1; i++)
        acc = fmaf(row[i], W_hz[i*EA_ + c], acc);
    g_h[(size_t)a*EA_ + c] = siluf(acc);
}

// ================= triplet scatter: 16 lanes x float4, red.v4 =================
__global__ void __launch_bounds__(256)
k_triplet(const int* __restrict__ ji, const int* __restrict__ kj,
          const float* __restrict__ Wcbf_b)
{
    __shared__ float4 w4[NS_][16];
    __shared__ float c1s[32];
    __shared__ int jis[32], kjs[32];
    int tid = threadIdx.x;
    w4[tid >> 4][tid & 15] = reinterpret_cast<const float4*>(Wcbf_b)[tid];
    int base = blockIdx.x * 32;
    if (tid < 32) {
        c1s[tid] = g_cth[base + tid];
        jis[tid] = ji[base + tid];
        kjs[tid] = kj[base + tid];
    }
    __syncthreads();
    int lane = tid & 15, tg = tid >> 4;
    #pragma unroll
    for (int it = 0; it < 2; it++) {
        int tt = it*16 + tg;
        float c1 = c1s[tt];
        float4 coef = w4[0][lane];
        float4 wv = w4[1][lane];
        coef.x = fmaf(wv.x, c1, coef.x);
        coef.y = fmaf(wv.y, c1, coef.y);
        coef.z = fmaf(wv.z, c1, coef.z);
        coef.w = fmaf(wv.w, c1, coef.w);
        float ck0 = 1.0f, ck1 = c1;
        #pragma unroll
        for (int k = 2; k < NS_; k++) {
            float ck = 2.0f*c1*ck1 - ck0;
            wv = w4[k][lane];
            coef.x = fmaf(wv.x, ck, coef.x);
            coef.y = fmaf(wv.y, ck, coef.y);
            coef.z = fmaf(wv.z, ck, coef.z);
            coef.w = fmaf(wv.w, ck, coef.w);
            ck0 = ck1; ck1 = ck;
        }
        int ekj = kjs[tt], eji = jis[tt];
        float4 xv = *reinterpret_cast<const float4*>(&g_x[(size_t)ekj*DT_ + lane*4]);
        float4 val;
        val.x = xv.x * coef.x; val.y = xv.y * coef.y;
        val.z = xv.z * coef.z; val.w = xv.w * coef.w;
        red4(&g_segE[(size_t)eji*DT_ + lane*4], val);
    }
}

__global__ void k_zero4(float4* __restrict__ p, int n4)
{
    int i = blockIdx.x * blockDim.x + threadIdx.x;
    if (i < n4) p[i] = make_float4(0.f, 0.f, 0.f, 0.f);
}

__global__ void k_pool(const int* __restrict__ natoms)
{
    int b = blockIdx.x, c = threadIdx.x;
    float s = 0.0f;
    #pragma unroll
    for (int i = 0; i < NA_; i++)
        s += g_X1[(size_t)(b*NA_ + i)*LAT_ + c];
    g_z[b*LAT_ + c] = s / (float)natoms[b];
}

template<int K_, int NN, bool RELU>
__global__ void k_fc(const float* __restrict__ X, const float* __restrict__ W,
                     const float* __restrict__ bias, float* __restrict__ Y)
{
    __shared__ float xr[K_];
    int r = blockIdx.x;
    for (int i = threadIdx.x; i < K_; i += blockDim.x) xr[i] = X[r*K_ + i];
    __syncthreads();
    for (int c = threadIdx.x; c < NN; c += blockDim.x) {
        float acc = bias[c];
        #pragma unroll 8
        for (int k = 0; k < K_; k++)
            acc = fmaf(xr[k], W[k*NN + c], acc);
        Y[r*NN + c] = RELU ? fmaxf(acc, 0.0f) : acc;
    }
}

// ================= SGEMM (large-M), packed f32x2 =================
// MODE 2: C += silu(acc)
// MODE 3: C = silu(acc + X1[src[r]] + X2[dst[r]])
template<int BM, int BN, int TM, int TN, int MODE>
__global__ void __launch_bounds__(256)
gemm_k(const float* __restrict__ A, const float* __restrict__ Bm,
       float* __restrict__ C, int K, const int* __restrict__ eidx)
{
    constexpr int BK  = 16;
    constexpr int BMp = BM + 4;
    constexpr int nA  = (BM*BK)/(4*256);
    constexpr int nB  = (BK*BN)/(4*256);
    __shared__ float As[2][BK][BMp];
    __shared__ float Bs[2][BK][BN];

    const int tid  = threadIdx.x;
    const int tx   = tid % (BN/TN);
    const int ty   = tid / (BN/TN);
    const int row0 = blockIdx.x * BM;

    float4 ra[nA], rb[nB];
    u64 acc2[TM][TN/2];
    #pragma unroll
    for (int i = 0; i < TM; i++)
        #pragma unroll
        for (int j = 0; j < TN/2; j++) acc2[i][j] = 0ull;

    auto ldg = [&](int k0) {
        #pragma unroll
        for (int i = 0; i < nA; i++) {
            int v = tid + i*256;
            ra[i] = *reinterpret_cast<const float4*>(
                &A[(size_t)(row0 + (v >> 2))*K + k0 + (v & 3)*4]);
        }
        #pragma unroll
        for (int i = 0; i < nB; i++) {
            int v = tid + i*256;
            rb[i] = *reinterpret_cast<const float4*>(
                &Bm[(size_t)(k0 + v/(BN/4))*BN + (v % (BN/4))*4]);
        }
    };
    auto sts = [&](int bsel) {
        #pragma unroll
        for (int i = 0; i < nA; i++) {
            int v = tid + i*256;
            int r = v >> 2, kq = (v & 3)*4;
            As[bsel][kq+0][r] = ra[i].x;
            As[bsel][kq+1][r] = ra[i].y;
            As[bsel][kq+2][r] = ra[i].z;
            As[bsel][kq+3][r] = ra[i].w;
        }
        #pragma unroll
        for (int i = 0; i < nB; i++) {
            int v = tid + i*256;
            *reinterpret_cast<float4*>(&Bs[bsel][v/(BN/4)][(v % (BN/4))*4]) = rb[i];
        }
    };
    auto compute = [&](int bsel) {
        #pragma unroll
        for (int k = 0; k < BK; k++) {
            float af[TM];
            u64   bf2[TN/2];
            *reinterpret_cast<float4*>(&af[0]) =
                *reinterpret_cast<const float4*>(&As[bsel][k][ty*4]);
            if constexpr (TM == 8)
                *reinterpret_cast<float4*>(&af[4]) =
                    *reinterpret_cast<const float4*>(&As[bsel][k][BM/2 + ty*4]);
            {
                const u64* bp = reinterpret_cast<const u64*>(&Bs[bsel][k][tx*4]);
                bf2[0] = bp[0]; bf2[1] = bp[1];
            }
            if constexpr (TN == 8) {
                const u64* bp = reinterpret_cast<const u64*>(&Bs[bsel][k][BN/2 + tx*4]);
                bf2[2] = bp[0]; bf2[3] = bp[1];
            }
            #pragma unroll
            for (int i = 0; i < TM; i++) {
                u64 a2 = pack2(af[i]);
                #pragma unroll
                for (int j = 0; j < TN/2; j++)
                    fma2(acc2[i][j], a2, bf2[j]);
            }
        }
    };

    ldg(0); sts(0);
    __syncthreads();
    int buf = 0;
    for (int k0 = BK; k0 < K; k0 += BK) {
        ldg(k0);
        compute(buf);
        sts(buf ^ 1);
        __syncthreads();
        buf ^= 1;
    }
    compute(buf);

    #pragma unroll
    for (int i = 0; i < TM; i++) {
        int rr = (TM == 8) ? ((i < 4) ? (ty*4 + i) : (BM/2 + ty*4 + i - 4))
                           : (ty*4 + i);
        int r = row0 + rr;
        float f[TN];
        #pragma unroll
        for (int j = 0; j < TN/2; j++) {
            float2 p = unpack2(acc2[i][j]);
            f[2*j] = p.x; f[2*j+1] = p.y;
        }
        int s = 0, d = 0;
        if constexpr (MODE == 3) { s = eidx[r]; d = eidx[E_ + r]; }
        #pragma unroll
        for (int jh = 0; jh < TN/4; jh++) {
            int c = jh*(BN/2) + tx*4;
            float4 v;
            v.x = f[jh*4+0]; v.y = f[jh*4+1];
            v.z = f[jh*4+2]; v.w = f[jh*4+3];
            float4* cp = reinterpret_cast<float4*>(&C[(size_t)r*BN + c]);
            if constexpr (MODE == 2) {
                float4 o = *cp;
                o.x += siluf(v.x); o.y += siluf(v.y);
                o.z += siluf(v.z); o.w += siluf(v.w);
                *cp = o;
            } else {
                float4 x1 = *reinterpret_cast<const float4*>(&g_X1[s*EE_ + c]);
                float4 x2 = *reinterpret_cast<const float4*>(&g_X2[d*EE_ + c]);
                float4 o;
                o.x = siluf(v.x + x1.x + x2.x);
                o.y = siluf(v.y + x1.y + x2.y);
                o.z = siluf(v.z + x1.z + x2.z);
                o.w = siluf(v.w + x1.w + x2.w);
                *cp = o;
            }
        }
    }
}

// ================= node GEMMs: BM=32, BK=32, f32x2 =================
template<int MODE>
__global__ void __launch_bounds__(256)
gemm32_k(const float* __restrict__ A,
         const float* __restrict__ B0, const float* __restrict__ B1,
         float* __restrict__ C0, float* __restrict__ C1, int K)
{
    constexpr int BM = 32, BN = 128, BK = 32, TM = 4;
    constexpr int BMp = BM + 4;
    __shared__ float As[2][BK][BMp];
    __shared__ float Bs[2][BK][BN];

    const float* Bm = blockIdx.y ? B1 : B0;
    float*       C  = blockIdx.y ? C1 : C0;

    const int tid = threadIdx.x;
    const int tx  = tid & 31;
    const int ty  = tid >> 5;
    const int row0 = blockIdx.x * BM;

    float4 ra, rb[4];
    u64 acc2[TM][2];
    #pragma unroll
    for (int i = 0; i < TM; i++) { acc2[i][0] = 0ull; acc2[i][1] = 0ull; }

    auto ldg = [&](int k0) {
        ra = *reinterpret_cast<const float4*>(
            &A[(size_t)(row0 + (tid >> 3))*K + k0 + (tid & 7)*4]);
        #pragma unroll
        for (int i = 0; i < 4; i++) {
            int v = tid + i*256;
            rb[i] = *reinterpret_cast<const float4*>(
                &Bm[(size_t)(k0 + (v >> 5))*BN + (v & 31)*4]);
        }
    };
    auto sts = [&](int bsel) {
        int r = tid >> 3, kq = (tid & 7)*4;
        As[bsel][kq+0][r] = ra.x;
        As[bsel][kq+1][r] = ra.y;
        As[bsel][kq+2][r] = ra.z;
        As[bsel][kq+3][r] = ra.w;
        #pragma unroll
        for (int i = 0; i < 4; i++) {
            int v = tid + i*256;
            *reinterpret_cast<float4*>(&Bs[bsel][v >> 5][(v & 31)*4]) = rb[i];
        }
    };
    auto compute = [&](int bsel) {
        #pragma unroll
        for (int k = 0; k < BK; k++) {
            float af[TM];
            *reinterpret_cast<float4*>(&af[0]) =
                *reinterpret_cast<const float4*>(&As[bsel][k][ty*4]);
            u64 bf2[2];
            const u64* bp = reinterpret_cast<const u64*>(&Bs[bsel][k][tx*4]);
            bf2[0] = bp[0]; bf2[1] = bp[1];
            #pragma unroll
            for (int i = 0; i < TM; i++) {
                u64 a2 = pack2(af[i]);
                fma2(acc2[i][0], a2, bf2[0]);
                fma2(acc2[i][1], a2, bf2[1]);
            }
        }
    };

    ldg(0); sts(0);
    __syncthreads();
    int buf = 0;
    for (int k0 = BK; k0 < K; k0 += BK) {
        ldg(k0);
        compute(buf);
        sts(buf ^ 1);
        __syncthreads();
        buf ^= 1;
    }
    compute(buf);

    #pragma unroll
    for (int i = 0; i < TM; i++) {
        size_t r = (size_t)(row0 + ty*4 + i);
        float2 p0 = unpack2(acc2[i][0]);
        float2 p1 = unpack2(acc2[i][1]);
        float4 v = make_float4(p0.x, p0.y, p1.x, p1.y);
        float4* cp = reinterpret_cast<float4*>(&C[r*BN + tx*4]);
        if constexpr (MODE == 0) {
            *cp = v;
        } else {
            float4 o = *cp;
            o.x += siluf(v.x); o.y += siluf(v.y);
            o.z += siluf(v.z); o.w += siluf(v.w);
            *cp = o;
        }
    }
}

// ================= fused dual GEMM + down-projection (+optional edgeupd fusion) ==========
__global__ void __launch_bounds__(256)
dual_down_k(const float* __restrict__ A1, const float* __restrict__ B1,
            const float* __restrict__ A2, const float* __restrict__ B2,
            const float* __restrict__ Wd, float* __restrict__ X,
            const int* __restrict__ eidx, int fuse)
{
    constexpr int BM = 64, BN = 128, BK = 16, TM = 4, TN = 8;
    constexpr int BMp = BM + 4;
    constexpr int K1 = EE_, K2 = NR_;
    __shared__ float As[2][BK][BMp];
    __shared__ float Bs[2][BK][BN];
    __shared__ float Ps[64][65];

    const int tid  = threadIdx.x;
    const int tx   = tid & 15;
    const int ty   = tid >> 4;
    const int row0 = blockIdx.x * BM;

    int s0 = 0, d0 = 0;
    if (fuse) {
        int rr = row0 + (tid >> 2);
        s0 = eidx[rr] * EE_;
        d0 = eidx[E_ + rr] * EE_;
    }

    u64 accA[TM][TN/2], accB[TM][TN/2];
    #pragma unroll
    for (int i = 0; i < TM; i++)
        #pragma unroll
        for (int j = 0; j < TN/2; j++) { accA[i][j] = 0ull; accB[i][j] = 0ull; }

    auto run = [&](const float* __restrict__ A, const float* __restrict__ Bm,
                   int K, u64 (*accp)[TN/2], bool doFuse) {
        float4 ra, rb0, rb1;
        auto ldg = [&](int k0) {
            int kc = k0 + (tid & 3)*4;
            size_t aoff = (size_t)(row0 + (tid >> 2))*K + kc;
            ra  = *reinterpret_cast<const float4*>(&A[aoff]);
            if (doFuse) {
                float4 aa = *reinterpret_cast<const float4*>(&g_hs[s0 + kc]);
                float4 bb = *reinterpret_cast<const float4*>(&g_ht[d0 + kc]);
                ra.x += siluf(aa.x + bb.x);
                ra.y += siluf(aa.y + bb.y);
                ra.z += siluf(aa.z + bb.z);
                ra.w += siluf(aa.w + bb.w);
                *reinterpret_cast<float4*>(const_cast<float*>(A) + aoff) = ra;
            }
            rb0 = *reinterpret_cast<const float4*>(
                &Bm[(size_t)(k0 + (tid >> 5))*BN + (tid & 31)*4]);
            rb1 = *reinterpret_cast<const float4*>(
                &Bm[(size_t)(k0 + 8 + (tid >> 5))*BN + (tid & 31)*4]);
        };
        auto sts = [&](int bsel) {
            int r = tid >> 2, kq = (tid & 3)*4;
            As[bsel][kq+0][r] = ra.x;
            As[bsel][kq+1][r] = ra.y;
            As[bsel][kq+2][r] = ra.z;
            As[bsel][kq+3][r] = ra.w;
            *reinterpret_cast<float4*>(&Bs[bsel][tid >> 5][(tid & 31)*4]) = rb0;
            *reinterpret_cast<float4*>(&Bs[bsel][8 + (tid >> 5)][(tid & 31)*4]) = rb1;
        };
        auto compute = [&](int bsel) {
            #pragma unroll
            for (int k = 0; k < BK; k++) {
                float af[TM];
                u64   bf2[TN/2];
                *reinterpret_cast<float4*>(&af[0]) =
                    *reinterpret_cast<const float4*>(&As[bsel][k][ty*4]);
                {
                    const u64* bp = reinterpret_cast<const u64*>(&Bs[bsel][k][tx*4]);
                    bf2[0] = bp[0]; bf2[1] = bp[1];
                }
                {
                    const u64* bp = reinterpret_cast<const u64*>(&Bs[bsel][k][64 + tx*4]);
                    bf2[2] = bp[0]; bf2[3] = bp[1];
                }
                #pragma unroll
                for (int i = 0; i < TM; i++) {
                    u64 a2 = pack2(af[i]);
                    #pragma unroll
                    for (int j = 0; j < TN/2; j++)
                        fma2(accp[i][j], a2, bf2[j]);
                }
            }
        };
        __syncthreads();
        ldg(0); sts(0);
        __syncthreads();
        int buf = 0;
        for (int k0 = BK; k0 < K; k0 += BK) {
            ldg(k0);
            compute(buf);
            sts(buf ^ 1);
            __syncthreads();
            buf ^= 1;
        }
        compute(buf);
    };

    run(A1, B1, K1, accA, fuse != 0);
    run(A2, B2, K2, accB, false);

    float (*Bs2)[BK][64] = reinterpret_cast<float (*)[BK][64]>(&As[0][0][0]);
    const int ty2 = tid >> 4;
    const int tx2 = tid & 15;
    u64 acc3[4][2];
    #pragma unroll
    for (int i = 0; i < 4; i++) { acc3[i][0] = 0ull; acc3[i][1] = 0ull; }

    #pragma unroll
    for (int half = 0; half < 2; half++) {
        __syncthreads();
        #pragma unroll
        for (int i = 0; i < TM; i++) {
            float2 pa0 = unpack2(accA[i][half*2+0]);
            float2 pa1 = unpack2(accA[i][half*2+1]);
            float2 pb0 = unpack2(accB[i][half*2+0]);
            float2 pb1 = unpack2(accB[i][half*2+1]);
            int mloc = ty*4 + i;
            Ps[tx*4+0][mloc] = siluf(pa0.x) * pb0.x;
            Ps[tx*4+1][mloc] = siluf(pa0.y) * pb0.y;
            Ps[tx*4+2][mloc] = siluf(pa1.x) * pb1.x;
            Ps[tx*4+3][mloc] = siluf(pa1.y) * pb1.y;
        }
        float4 rw;
        auto ldgW = [&](int kt) {
            rw = *reinterpret_cast<const float4*>(
                &Wd[(size_t)(half*64 + kt + (tid >> 4))*DT_ + (tid & 15)*4]);
        };
        auto stsW = [&](int bsel) {
            *reinterpret_cast<float4*>(&Bs2[bsel][tid >> 4][(tid & 15)*4]) = rw;
        };
        auto computeW = [&](int bsel, int kt) {
            #pragma unroll
            for (int k = 0; k < BK; k++) {
                float af[4];
                #pragma unroll
                for (int i = 0; i < 4; i++)
                    af[i] = Ps[kt + k][ty2*4 + i];
                u64 bf2[2];
                const u64* bp = reinterpret_cast<const u64*>(&Bs2[bsel][k][tx2*4]);
                bf2[0] = bp[0]; bf2[1] = bp[1];
                #pragma unroll
                for (int i = 0; i < 4; i++) {
                    u64 a2 = pack2(af[i]);
                    fma2(acc3[i][0], a2, bf2[0]);
                    fma2(acc3[i][1], a2, bf2[1]);
                }
            }
        };
        ldgW(0);
        __syncthreads();
        stsW(0);
        __syncthreads();
        int buf = 0;
        #pragma unroll
        for (int kt = BK; kt < 64; kt += BK) {
            ldgW(kt);
            computeW(buf, kt - BK);
            stsW(buf ^ 1);
            __syncthreads();
            buf ^= 1;
        }
        computeW(buf, 64 - BK);
    }

    #pragma unroll
    for (int i = 0; i < 4; i++) {
        size_t r = (size_t)(row0 + ty2*4 + i);
        float2 p0 = unpack2(acc3[i][0]);
        float2 p1 = unpack2(acc3[i][1]);
        float4 v = make_float4(p0.x, p0.y, p1.x, p1.y);
        *reinterpret_cast<float4*>(&X[r*DT_ + tx2*4]) = v;
    }
}

// ================= dual GEMM with dst-scatter (red.v4) =================
__global__ void __launch_bounds__(256)
dual_scat_k(const float* __restrict__ A1, const float* __restrict__ B1, int K1,
            const float* __restrict__ A2, const float* __restrict__ B2, int K2,
            float* __restrict__ C, const int* __restrict__ dstIdx)
{
    constexpr int BM = 64, BN = 128, BK = 16, TM = 4, TN = 8;
    constexpr int BMp = BM + 4;
    __shared__ float As[2][BK][BMp];
    __shared__ float Bs[2][BK][BN];

    const int tid  = threadIdx.x;
    const int tx   = tid & 15;
    const int ty   = tid >> 4;
    const int row0 = blockIdx.x * BM;

    u64 accA[TM][TN/2], accB[TM][TN/2];
    #pragma unroll
    for (int i = 0; i < TM; i++)
        #pragma unroll
        for (int j = 0; j < TN/2; j++) { accA[i][j] = 0ull; accB[i][j] = 0ull; }

    auto run = [&](const float* __restrict__ A, const float* __restrict__ Bm,
                   int K, u64 (*accp)[TN/2]) {
        float4 ra, rb0, rb1;
        auto ldg = [&](int k0) {
            ra  = *reinterpret_cast<const float4*>(
                &A[(size_t)(row0 + (tid >> 2))*K + k0 + (tid & 3)*4]);
            rb0 = *reinterpret_cast<const float4*>(
                &Bm[(size_t)(k0 + (tid >> 5))*BN + (tid & 31)*4]);
            rb1 = *reinterpret_cast<const float4*>(
                &Bm[(size_t)(k0 + 8 + (tid >> 5))*BN + (tid & 31)*4]);
        };
        auto sts = [&](int bsel) {
            int r = tid >> 2, kq = (tid & 3)*4;
            As[bsel][kq+0][r] = ra.x;
            As[bsel][kq+1][r] = ra.y;
            As[bsel][kq+2][r] = ra.z;
            As[bsel][kq+3][r] = ra.w;
            *reinterpret_cast<float4*>(&Bs[bsel][tid >> 5][(tid & 31)*4]) = rb0;
            *reinterpret_cast<float4*>(&Bs[bsel][8 + (tid >> 5)][(tid & 31)*4]) = rb1;
        };
        auto compute = [&](int bsel) {
            #pragma unroll
            for (int k = 0; k < BK; k++) {
                float af[TM];
                u64   bf2[TN/2];
                *reinterpret_cast<float4*>(&af[0]) =
                    *reinterpret_cast<const float4*>(&As[bsel][k][ty*4]);
                {
                    const u64* bp = reinterpret_cast<const u64*>(&Bs[bsel][k][tx*4]);
                    bf2[0] = bp[0]; bf2[1] = bp[1];
                }
                {
                    const u64* bp = reinterpret_cast<const u64*>(&Bs[bsel][k][64 + tx*4]);
                    bf2[2] = bp[0]; bf2[3] = bp[1];
                }
                #pragma unroll
                for (int i = 0; i < TM; i++) {
                    u64 a2 = pack2(af[i]);
                    #pragma unroll
                    for (int j = 0; j < TN/2; j++)
                        fma2(accp[i][j], a2, bf2[j]);
                }
            }
        };
        __syncthreads();
        ldg(0); sts(0);
        __syncthreads();
        int buf = 0;
        for (int k0 = BK; k0 < K; k0 += BK) {
            ldg(k0);
            compute(buf);
            sts(buf ^ 1);
            __syncthreads();
            buf ^= 1;
        }
        compute(buf);
    };

    run(A1, B1, K1, accA);
    run(A2, B2, K2, accB);

    #pragma unroll
    for (int i = 0; i < TM; i++) {
        int r = row0 + ty*4 + i;
        int dr = dstIdx[r];
        float2 pa0 = unpack2(accA[i][0]), pb0 = unpack2(accB[i][0]);
        float2 pa1 = unpack2(accA[i][1]), pb1 = unpack2(accB[i][1]);
        float4 v0 = make_float4(siluf(pa0.x)*pb0.x, siluf(pa0.y)*pb0.y,
                                siluf(pa1.x)*pb1.x, siluf(pa1.y)*pb1.y);
        red4(&C[(size_t)dr*128 + tx*4], v0);
        float2 pa2 = unpack2(accA[i][2]), pb2 = unpack2(accB[i][2]);
        float2 pa3 = unpack2(accA[i][3]), pb3 = unpack2(accB[i][3]);
        float4 v1 = make_float4(siluf(pa2.x)*pb2.x, siluf(pa2.y)*pb2.y,
                                siluf(pa3.x)*pb3.x, siluf(pa3.y)*pb3.y);
        red4(&C[(size_t)dr*128 + 64 + tx*4], v1);
    }
}

// ---------------- launch ----------------
extern "C" void kernel_launch(void* const* d_in, const int* in_sizes, int n_in,
                              void* d_out, int out_size)
{
    const float* noise   = (const float*)d_in[0];
    const float* frac    = (const float*)d_in[1];
    const float* lengths = (const float*)d_in[2];
    const float* angles  = (const float*)d_in[3];
    const int*   atype   = (const int*)  d_in[4];
    const int*   natoms  = (const int*)  d_in[5];
    const int*   ei      = (const int*)  d_in[6];
    const int*   ji      = (const int*)  d_in[7];
    const int*   kj      = (const int*)  d_in[8];
    const float* emb     = (const float*)d_in[9];
    const float* W_hz    = (const float*)d_in[10];
    const float* W_edge  = (const float*)d_in[11];
    const float* Wm      = (const float*)d_in[12];
    const float* Wr1     = (const float*)d_in[13];
    const float* Wdown   = (const float*)d_in[14];
    const float* Wcbf    = (const float*)d_in[15];
    const float* Wup     = (const float*)d_in[16];
    const float* Wa      = (const float*)d_in[17];
    const float* Wr2     = (const float*)d_in[18];
    const float* Wh      = (const float*)d_in[19];
    const float* Ws      = (const float*)d_in[20];
    const float* Wt      = (const float*)d_in[21];
    const float* W_out   = (const float*)d_in[22];
    const float* W_fc0   = (const float*)d_in[23];
    const float* b_fc0   = (const float*)d_in[24];
    const float* W_fc1   = (const float*)d_in[25];
    const float* b_fc1   = (const float*)d_in[26];
    const float* W_fc2   = (const float*)d_in[27];
    const float* b_fc2   = (const float*)d_in[28];
    float* out = (float*)d_out;

    float *p_h, *p_X1, *p_X2, *p_m, *p_x, *p_segE, *p_aN,
          *p_hs, *p_ht, *p_rbf, *p_z, *p_f0, *p_f1;
    cudaGetSymbolAddress((void**)&p_h,    g_h);
    cudaGetSymbolAddress((void**)&p_X1,   g_X1);
    cudaGetSymbolAddress((void**)&p_X2,   g_X2);
    cudaGetSymbolAddress((void**)&p_m,    g_m);
    cudaGetSymbolAddress((void**)&p_x,    g_x);
    cudaGetSymbolAddress((void**)&p_segE, g_segE);
    cudaGetSymbolAddress((void**)&p_aN,   g_aN);
    cudaGetSymbolAddress((void**)&p_hs,   g_hs);
    cudaGetSymbolAddress((void**)&p_ht,   g_ht);
    cudaGetSymbolAddress((void**)&p_rbf,  g_rbf);
    cudaGetSymbolAddress((void**)&p_z,    g_z);
    cudaGetSymbolAddress((void**)&p_f0,   g_f0);
    cudaGetSymbolAddress((void**)&p_f1,   g_f1);

    // ---- geometry ----
    k_pos<<<(N_ + 255)/256, 256>>>(frac, lengths, angles);
    k_edge<<<E_/256, 256>>>(ei);
    k_cth<<<T_/256, 256>>>(ji, kj);
    k_h<<<N_, EA_>>>(atype, noise, emb, W_hz);

    // ---- m init ----
    gemm32_k<0><<<dim3(N_/32, 2), 256>>>(p_h, W_edge, W_edge + 128*EE_,
                                         p_X1, p_X2, EA_);
    gemm_k<128,128,8,8,3><<<E_/128, 256>>>(p_rbf, W_edge + 256*EE_, p_m, NR_, ei);

    for (int b = 0; b < NB_; b++) {
        const float* Wm_b    = Wm    + (size_t)b*EE_*EE_;
        const float* Wr1_b   = Wr1   + (size_t)b*NR_*EE_;
        const float* Wdown_b = Wdown + (size_t)b*EE_*DT_;
        const float* Wcbf_b  = Wcbf  + (size_t)b*NS_*DT_;
        const float* Wup_b   = Wup   + (size_t)b*DT_*EE_;
        const float* Wa_b    = Wa    + (size_t)b*EE_*EA_;
        const float* Wr2_b   = Wr2   + (size_t)b*NR_*EA_;
        const float* Wh_b    = Wh    + (size_t)b*EA_*EA_;
        const float* Ws_b    = Ws    + (size_t)b*EA_*EE_;
        const float* Wt_b    = Wt    + (size_t)b*EA_*EE_;

        // x = (silu(m'@Wm) * (rbf@Wr1)) @ Wdown;  m' applies prev iter's edge update
        dual_down_k<<<E_/64, 256>>>(p_m, Wm_b, p_rbf, Wr1_b, Wdown_b, p_x,
                                    ei, (b > 0) ? 1 : 0);

        // triplet aggregation (red.v4 scatter)
        k_zero4<<<(E_*DT_/4 + 255)/256, 256>>>((float4*)p_segE, E_*DT_/4);
        k_triplet<<<T_/32, 256>>>(ji, kj, Wcbf_b);

        // m += silu(segE @ Wup)
        gemm_k<128,128,8,8,2><<<E_/128, 256>>>(p_segE, Wup_b, p_m, DT_, (const int*)0);

        // aN = scatter_dst( silu(m@Wa) * (rbf@Wr2) )
        k_zero4<<<(N_*EA_/4 + 255)/256, 256>>>((float4*)p_aN, N_*EA_/4);
        dual_scat_k<<<E_/64, 256>>>(p_m, Wa_b, EE_, p_rbf, Wr2_b, NR_, p_aN, ei + E_);

        // h += silu(aN @ Wh)
        gemm32_k<2><<<dim3(N_/32, 1), 256>>>(p_aN, Wh_b, Wh_b, p_h, p_h, EA_);

        // hs/ht for next iter's fused edge update (dead after the final block)
        if (b < NB_ - 1) {
            gemm32_k<0><<<dim3(N_/32, 2), 256>>>(p_h, Ws_b, Wt_b, p_hs, p_ht, EA_);
        }
    }

    // ---- readout ----
    gemm32_k<0><<<dim3(N_/32, 1), 256>>>(p_h, W_out, W_out, p_X1, p_X1, EA_);
    k_pool<<<B_, LAT_>>>(natoms);

    k_fc<LAT_, HID_, true ><<<B_, 256>>>(p_z,  W_fc0, b_fc0, p_f0);
    k_fc<HID_, HID_, true ><<<B_, 256>>>(p_f0, W_fc1, b_fc1, p_f1);
    k_fc<HID_, NC_,  false><<<B_, 256>>>(p_f1, W_fc2, b_fc2, out);
}

// round 16
// speedup vs baseline: 1.0094x; 1.0094x over previous
#include <cuda_runtime.h>
#include <math.h>

#define B_    128
#define NA_   32
#define N_    4096
#define E_    65536
#define T_    262144
#define EA_   128
#define EE_   128
#define DT_   64
#define NR_   64
#define NS_   16
#define NB_   3
#define LAT_  128
#define HID_  256
#define NC_   230
#define PI_F  3.14159265358979323846f

typedef unsigned long long u64;

__device__ __forceinline__ void fma2(u64& d, u64 a, u64 b) {
    asm("fma.rn.f32x2 %0, %1, %2, %0;" : "+l"(d) : "l"(a), "l"(b));
}
__device__ __forceinline__ u64 pack2(float x) {
    u64 r; asm("mov.b64 %0, {%1, %1};" : "=l"(r) : "f"(x)); return r;
}
__device__ __forceinline__ float2 unpack2(u64 v) {
    float2 r; asm("mov.b64 {%0, %1}, %2;" : "=f"(r.x), "=f"(r.y) : "l"(v)); return r;
}
__device__ __forceinline__ void red4(float* p, float4 v) {
    asm volatile("red.global.add.v4.f32 [%0], {%1, %2, %3, %4};"
                 :: "l"(p), "f"(v.x), "f"(v.y), "f"(v.z), "f"(v.w) : "memory");
}

// ---- scratch ----
__device__ float g_pos [N_*3];
__device__ float g_vec [E_*3];
__device__ float g_rbf [E_*NR_];
__device__ float g_cth [T_];
__device__ float g_h   [N_*EA_];
__device__ float g_X1  [N_*EE_];
__device__ float g_X2  [N_*EE_];
__device__ float g_m   [E_*EE_];
__device__ float g_x   [E_*DT_];
__device__ float g_segE[E_*DT_];
__device__ float g_aN  [N_*EA_];
__device__ float g_hs  [N_*EA_];
__device__ float g_ht  [N_*EA_];
__device__ float g_z   [B_*LAT_];
__device__ float g_f0  [B_*HID_];
__device__ float g_f1  [B_*HID_];

__device__ __forceinline__ float siluf(float v) {
    return v * (1.0f / (1.0f + __expf(-v)));
}

// ================= geometry =================
__global__ void k_pos(const float* __restrict__ frac,
                      const float* __restrict__ lengths,
                      const float* __restrict__ angles)
{
    int n = blockIdx.x * blockDim.x + threadIdx.x;
    if (n >= N_) return;
    int b = n / NA_;
    float a  = lengths[b*3+0], bb = lengths[b*3+1], c = lengths[b*3+2];
    float al = angles[b*3+0] * (PI_F/180.0f);
    float be = angles[b*3+1] * (PI_F/180.0f);
    float ga = angles[b*3+2] * (PI_F/180.0f);
    float ca = cosf(al), cb = cosf(be), cg = cosf(ga), sg = sinf(ga);
    float cx = cb;
    float cy = (ca - cb*cg) / sg;
    float cz = sqrtf(fmaxf(1.0f - cx*cx - cy*cy, 1e-8f));
    float f0 = frac[n*3+0], f1 = frac[n*3+1], f2 = frac[n*3+2];
    g_pos[n*3+0] = f0*a + f1*bb*cg + f2*c*cx;
    g_pos[n*3+1] =        f1*bb*sg + f2*c*cy;
    g_pos[n*3+2] =                   f2*c*cz;
}

// thread-per-edge; one sincosf + sine recurrence for all 64 terms.
__global__ void k_edge(const int* __restrict__ ei)
{
    int e = blockIdx.x * blockDim.x + threadIdx.x;
    if (e >= E_) return;
    int s = ei[e], dd = ei[E_ + e];
    float vx = g_pos[dd*3+0] - g_pos[s*3+0];
    float vy = g_pos[dd*3+1] - g_pos[s*3+1];
    float vz = g_pos[dd*3+2] - g_pos[s*3+2];
    g_vec[e*3+0] = vx; g_vec[e*3+1] = vy; g_vec[e*3+2] = vz;
    float d  = sqrtf(vx*vx + vy*vy + vz*vz + 1e-12f);
    float ds = d * (1.0f / 7.0f);
    float env = 0.0f;
    if (ds < 1.0f) {
        float d2 = ds*ds; float d4 = d2*d2; float d5 = d4*ds;
        env = 1.0f - 21.0f*d5 + 35.0f*d5*ds - 15.0f*d5*d2;
    }
    float coef = env * sqrtf(2.0f/7.0f) / d;
    float th = PI_F * ds;
    float s1, c1;
    sincosf(th, &s1, &c1);
    float c2 = 2.0f * c1;
    float sp = 0.0f, sn = s1;
    float* row = &g_rbf[(size_t)e * NR_];
    #pragma unroll
    for (int q = 0; q < NR_/4; q++) {
        float4 v;
        v.x = coef * sn; { float t = c2*sn - sp; sp = sn; sn = t; }
        v.y = coef * sn; { float t = c2*sn - sp; sp = sn; sn = t; }
        v.z = coef * sn; { float t = c2*sn - sp; sp = sn; sn = t; }
        v.w = coef * sn; { float t = c2*sn - sp; sp = sn; sn = t; }
        *reinterpret_cast<float4*>(&row[q*4]) = v;
    }
}

__global__ void k_cth(const int* __restrict__ ji, const int* __restrict__ kj)
{
    int t = blockIdx.x * blockDim.x + threadIdx.x;
    if (t >= T_) return;
    int a = ji[t], b = kj[t];
    float ax = g_vec[a*3+0], ay = g_vec[a*3+1], az = g_vec[a*3+2];
    float bx = g_vec[b*3+0], by = g_vec[b*3+1], bz = g_vec[b*3+2];
    float dot = ax*bx + ay*by + az*bz;
    float n1  = sqrtf(ax*ax + ay*ay + az*az);
    float n2  = sqrtf(bx*bx + by*by + bz*bz);
    float c   = dot / (n1*n2 + 1e-9f);
    g_cth[t] = fminf(fmaxf(c, -1.0f + 1e-6f), 1.0f - 1e-6f);
}

// ================= node features =================
__global__ void k_h(const int* __restrict__ atype,
                    const float* __restrict__ noise,
                    const float* __restrict__ emb,
                    const float* __restrict__ W_hz)
{
    __shared__ float row[EA_ + 1];
    int a = blockIdx.x, c = threadIdx.x;
    int ty = atype[a];
    row[c] = emb[ty*EA_ + c];
    if (c == 0) row[EA_] = noise[a / NA_];
    __syncthreads();
    float acc = 0.0f;
    #pragma unroll 8
    for (int i = 0; i < EA_ + 1; i++)
        acc = fmaf(row[i], W_hz[i*EA_ + c], acc);
    g_h[(size_t)a*EA_ + c] = siluf(acc);
}

// ================= triplet scatter: 16 lanes x float4, red.v4 =================
__global__ void __launch_bounds__(256)
k_triplet(const int* __restrict__ ji, const int* __restrict__ kj,
          const float* __restrict__ Wcbf_b)
{
    __shared__ float4 w4[NS_][16];
    __shared__ float c1s[32];
    __shared__ int jis[32], kjs[32];
    int tid = threadIdx.x;
    w4[tid >> 4][tid & 15] = reinterpret_cast<const float4*>(Wcbf_b)[tid];
    int base = blockIdx.x * 32;
    if (tid < 32) {
        c1s[tid] = g_cth[base + tid];
        jis[tid] = ji[base + tid];
        kjs[tid] = kj[base + tid];
    }
    __syncthreads();
    int lane = tid & 15, tg = tid >> 4;
    #pragma unroll
    for (int it = 0; it < 2; it++) {
        int tt = it*16 + tg;
        float c1 = c1s[tt];
        float4 coef = w4[0][lane];
        float4 wv = w4[1][lane];
        coef.x = fmaf(wv.x, c1, coef.x);
        coef.y = fmaf(wv.y, c1, coef.y);
        coef.z = fmaf(wv.z, c1, coef.z);
        coef.w = fmaf(wv.w, c1, coef.w);
        float ck0 = 1.0f, ck1 = c1;
        #pragma unroll
        for (int k = 2; k < NS_; k++) {
            float ck = 2.0f*c1*ck1 - ck0;
            wv = w4[k][lane];
            coef.x = fmaf(wv.x, ck, coef.x);
            coef.y = fmaf(wv.y, ck, coef.y);
            coef.z = fmaf(wv.z, ck, coef.z);
            coef.w = fmaf(wv.w, ck, coef.w);
            ck0 = ck1; ck1 = ck;
        }
        int ekj = kjs[tt], eji = jis[tt];
        float4 xv = *reinterpret_cast<const float4*>(&g_x[(size_t)ekj*DT_ + lane*4]);
        float4 val;
        val.x = xv.x * coef.x; val.y = xv.y * coef.y;
        val.z = xv.z * coef.z; val.w = xv.w * coef.w;
        red4(&g_segE[(size_t)eji*DT_ + lane*4], val);
    }
}

__global__ void k_zero4(float4* __restrict__ p, int n4)
{
    int i = blockIdx.x * blockDim.x + threadIdx.x;
    if (i < n4) p[i] = make_float4(0.f, 0.f, 0.f, 0.f);
}

__global__ void k_pool(const int* __restrict__ natoms)
{
    int b = blockIdx.x, c = threadIdx.x;
    float s = 0.0f;
    #pragma unroll
    for (int i = 0; i < NA_; i++)
        s += g_X1[(size_t)(b*NA_ + i)*LAT_ + c];
    g_z[b*LAT_ + c] = s / (float)natoms[b];
}

template<int K_, int NN, bool RELU>
__global__ void k_fc(const float* __restrict__ X, const float* __restrict__ W,
                     const float* __restrict__ bias, float* __restrict__ Y)
{
    __shared__ float xr[K_];
    int r = blockIdx.x;
    for (int i = threadIdx.x; i < K_; i += blockDim.x) xr[i] = X[r*K_ + i];
    __syncthreads();
    for (int c = threadIdx.x; c < NN; c += blockDim.x) {
        float acc = bias[c];
        #pragma unroll 8
        for (int k = 0; k < K_; k++)
            acc = fmaf(xr[k], W[k*NN + c], acc);
        Y[r*NN + c] = RELU ? fmaxf(acc, 0.0f) : acc;
    }
}

// ================= SGEMM (large-M) MODE 3: m-init fusion =================
__global__ void __launch_bounds__(256)
gemm_k(const float* __restrict__ A, const float* __restrict__ Bm,
       float* __restrict__ C, int K, const int* __restrict__ eidx)
{
    constexpr int BM = 128, BN = 128, BK = 16, TM = 8, TN = 8;
    constexpr int BMp = BM + 4;
    constexpr int nA  = (BM*BK)/(4*256);
    constexpr int nB  = (BK*BN)/(4*256);
    __shared__ float As[2][BK][BMp];
    __shared__ float Bs[2][BK][BN];

    const int tid  = threadIdx.x;
    const int tx   = tid % (BN/TN);
    const int ty   = tid / (BN/TN);
    const int row0 = blockIdx.x * BM;

    float4 ra[nA], rb[nB];
    u64 acc2[TM][TN/2];
    #pragma unroll
    for (int i = 0; i < TM; i++)
        #pragma unroll
        for (int j = 0; j < TN/2; j++) acc2[i][j] = 0ull;

    auto ldg = [&](int k0) {
        #pragma unroll
        for (int i = 0; i < nA; i++) {
            int v = tid + i*256;
            ra[i] = *reinterpret_cast<const float4*>(
                &A[(size_t)(row0 + (v >> 2))*K + k0 + (v & 3)*4]);
        }
        #pragma unroll
        for (int i = 0; i < nB; i++) {
            int v = tid + i*256;
            rb[i] = *reinterpret_cast<const float4*>(
                &Bm[(size_t)(k0 + v/(BN/4))*BN + (v % (BN/4))*4]);
        }
    };
    auto sts = [&](int bsel) {
        #pragma unroll
        for (int i = 0; i < nA; i++) {
            int v = tid + i*256;
            int r = v >> 2, kq = (v & 3)*4;
            As[bsel][kq+0][r] = ra[i].x;
            As[bsel][kq+1][r] = ra[i].y;
            As[bsel][kq+2][r] = ra[i].z;
            As[bsel][kq+3][r] = ra[i].w;
        }
        #pragma unroll
        for (int i = 0; i < nB; i++) {
            int v = tid + i*256;
            *reinterpret_cast<float4*>(&Bs[bsel][v/(BN/4)][(v % (BN/4))*4]) = rb[i];
        }
    };
    auto compute = [&](int bsel) {
        #pragma unroll
        for (int k = 0; k < BK; k++) {
            float af[TM];
            u64   bf2[TN/2];
            *reinterpret_cast<float4*>(&af[0]) =
                *reinterpret_cast<const float4*>(&As[bsel][k][ty*4]);
            *reinterpret_cast<float4*>(&af[4]) =
                *reinterpret_cast<const float4*>(&As[bsel][k][BM/2 + ty*4]);
            {
                const u64* bp = reinterpret_cast<const u64*>(&Bs[bsel][k][tx*4]);
                bf2[0] = bp[0]; bf2[1] = bp[1];
            }
            {
                const u64* bp = reinterpret_cast<const u64*>(&Bs[bsel][k][BN/2 + tx*4]);
                bf2[2] = bp[0]; bf2[3] = bp[1];
            }
            #pragma unroll
            for (int i = 0; i < TM; i++) {
                u64 a2 = pack2(af[i]);
                #pragma unroll
                for (int j = 0; j < TN/2; j++)
                    fma2(acc2[i][j], a2, bf2[j]);
            }
        }
    };

    ldg(0); sts(0);
    __syncthreads();
    int buf = 0;
    for (int k0 = BK; k0 < K; k0 += BK) {
        ldg(k0);
        compute(buf);
        sts(buf ^ 1);
        __syncthreads();
        buf ^= 1;
    }
    compute(buf);

    #pragma unroll
    for (int i = 0; i < TM; i++) {
        int rr = (i < 4) ? (ty*4 + i) : (BM/2 + ty*4 + i - 4);
        int r = row0 + rr;
        float f[TN];
        #pragma unroll
        for (int j = 0; j < TN/2; j++) {
            float2 p = unpack2(acc2[i][j]);
            f[2*j] = p.x; f[2*j+1] = p.y;
        }
        int s = eidx[r], d = eidx[E_ + r];
        #pragma unroll
        for (int jh = 0; jh < TN/4; jh++) {
            int c = jh*(BN/2) + tx*4;
            float4 x1 = *reinterpret_cast<const float4*>(&g_X1[s*EE_ + c]);
            float4 x2 = *reinterpret_cast<const float4*>(&g_X2[d*EE_ + c]);
            float4 o;
            o.x = siluf(f[jh*4+0] + x1.x + x2.x);
            o.y = siluf(f[jh*4+1] + x1.y + x2.y);
            o.z = siluf(f[jh*4+2] + x1.z + x2.z);
            o.w = siluf(f[jh*4+3] + x1.w + x2.w);
            *reinterpret_cast<float4*>(&C[(size_t)r*BN + c]) = o;
        }
    }
}

// ================= node GEMMs: BM=32, BK=32, f32x2 =================
template<int MODE>
__global__ void __launch_bounds__(256)
gemm32_k(const float* __restrict__ A,
         const float* __restrict__ B0, const float* __restrict__ B1,
         float* __restrict__ C0, float* __restrict__ C1, int K)
{
    constexpr int BM = 32, BN = 128, BK = 32, TM = 4;
    constexpr int BMp = BM + 4;
    __shared__ float As[2][BK][BMp];
    __shared__ float Bs[2][BK][BN];

    const float* Bm = blockIdx.y ? B1 : B0;
    float*       C  = blockIdx.y ? C1 : C0;

    const int tid = threadIdx.x;
    const int tx  = tid & 31;
    const int ty  = tid >> 5;
    const int row0 = blockIdx.x * BM;

    float4 ra, rb[4];
    u64 acc2[TM][2];
    #pragma unroll
    for (int i = 0; i < TM; i++) { acc2[i][0] = 0ull; acc2[i][1] = 0ull; }

    auto ldg = [&](int k0) {
        ra = *reinterpret_cast<const float4*>(
            &A[(size_t)(row0 + (tid >> 3))*K + k0 + (tid & 7)*4]);
        #pragma unroll
        for (int i = 0; i < 4; i++) {
            int v = tid + i*256;
            rb[i] = *reinterpret_cast<const float4*>(
                &Bm[(size_t)(k0 + (v >> 5))*BN + (v & 31)*4]);
        }
    };
    auto sts = [&](int bsel) {
        int r = tid >> 3, kq = (tid & 7)*4;
        As[bsel][kq+0][r] = ra.x;
        As[bsel][kq+1][r] = ra.y;
        As[bsel][kq+2][r] = ra.z;
        As[bsel][kq+3][r] = ra.w;
        #pragma unroll
        for (int i = 0; i < 4; i++) {
            int v = tid + i*256;
            *reinterpret_cast<float4*>(&Bs[bsel][v >> 5][(v & 31)*4]) = rb[i];
        }
    };
    auto compute = [&](int bsel) {
        #pragma unroll
        for (int k = 0; k < BK; k++) {
            float af[TM];
            *reinterpret_cast<float4*>(&af[0]) =
                *reinterpret_cast<const float4*>(&As[bsel][k][ty*4]);
            u64 bf2[2];
            const u64* bp = reinterpret_cast<const u64*>(&Bs[bsel][k][tx*4]);
            bf2[0] = bp[0]; bf2[1] = bp[1];
            #pragma unroll
            for (int i = 0; i < TM; i++) {
                u64 a2 = pack2(af[i]);
                fma2(acc2[i][0], a2, bf2[0]);
                fma2(acc2[i][1], a2, bf2[1]);
            }
        }
    };

    ldg(0); sts(0);
    __syncthreads();
    int buf = 0;
    for (int k0 = BK; k0 < K; k0 += BK) {
        ldg(k0);
        compute(buf);
        sts(buf ^ 1);
        __syncthreads();
        buf ^= 1;
    }
    compute(buf);

    #pragma unroll
    for (int i = 0; i < TM; i++) {
        size_t r = (size_t)(row0 + ty*4 + i);
        float2 p0 = unpack2(acc2[i][0]);
        float2 p1 = unpack2(acc2[i][1]);
        float4 v = make_float4(p0.x, p0.y, p1.x, p1.y);
        float4* cp = reinterpret_cast<float4*>(&C[r*BN + tx*4]);
        if constexpr (MODE == 0) {
            *cp = v;
        } else {
            float4 o = *cp;
            o.x += siluf(v.x); o.y += siluf(v.y);
            o.z += siluf(v.z); o.w += siluf(v.w);
            *cp = o;
        }
    }
}

// ================= fused dual GEMM + down-projection (+optional edgeupd fusion) ==========
__global__ void __launch_bounds__(256)
dual_down_k(const float* __restrict__ A1, const float* __restrict__ B1,
            const float* __restrict__ A2, const float* __restrict__ B2,
            const float* __restrict__ Wd, float* __restrict__ X,
            const int* __restrict__ eidx, int fuse)
{
    constexpr int BM = 64, BN = 128, BK = 16, TM = 4, TN = 8;
    constexpr int BMp = BM + 4;
    constexpr int K1 = EE_, K2 = NR_;
    __shared__ float As[2][BK][BMp];
    __shared__ float Bs[2][BK][BN];
    __shared__ float Ps[64][65];

    const int tid  = threadIdx.x;
    const int tx   = tid & 15;
    const int ty   = tid >> 4;
    const int row0 = blockIdx.x * BM;

    int s0 = 0, d0 = 0;
    if (fuse) {
        int rr = row0 + (tid >> 2);
        s0 = eidx[rr] * EE_;
        d0 = eidx[E_ + rr] * EE_;
    }

    u64 accA[TM][TN/2], accB[TM][TN/2];
    #pragma unroll
    for (int i = 0; i < TM; i++)
        #pragma unroll
        for (int j = 0; j < TN/2; j++) { accA[i][j] = 0ull; accB[i][j] = 0ull; }

    auto run = [&](const float* __restrict__ A, const float* __restrict__ Bm,
                   int K, u64 (*accp)[TN/2], bool doFuse) {
        float4 ra, rb0, rb1;
        auto ldg = [&](int k0) {
            int kc = k0 + (tid & 3)*4;
            size_t aoff = (size_t)(row0 + (tid >> 2))*K + kc;
            ra  = *reinterpret_cast<const float4*>(&A[aoff]);
            if (doFuse) {
                float4 aa = *reinterpret_cast<const float4*>(&g_hs[s0 + kc]);
                float4 bb = *reinterpret_cast<const float4*>(&g_ht[d0 + kc]);
                ra.x += siluf(aa.x + bb.x);
                ra.y += siluf(aa.y + bb.y);
                ra.z += siluf(aa.z + bb.z);
                ra.w += siluf(aa.w + bb.w);
                *reinterpret_cast<float4*>(const_cast<float*>(A) + aoff) = ra;
            }
            rb0 = *reinterpret_cast<const float4*>(
                &Bm[(size_t)(k0 + (tid >> 5))*BN + (tid & 31)*4]);
            rb1 = *reinterpret_cast<const float4*>(
                &Bm[(size_t)(k0 + 8 + (tid >> 5))*BN + (tid & 31)*4]);
        };
        auto sts = [&](int bsel) {
            int r = tid >> 2, kq = (tid & 3)*4;
            As[bsel][kq+0][r] = ra.x;
            As[bsel][kq+1][r] = ra.y;
            As[bsel][kq+2][r] = ra.z;
            As[bsel][kq+3][r] = ra.w;
            *reinterpret_cast<float4*>(&Bs[bsel][tid >> 5][(tid & 31)*4]) = rb0;
            *reinterpret_cast<float4*>(&Bs[bsel][8 + (tid >> 5)][(tid & 31)*4]) = rb1;
        };
        auto compute = [&](int bsel) {
            #pragma unroll
            for (int k = 0; k < BK; k++) {
                float af[TM];
                u64   bf2[TN/2];
                *reinterpret_cast<float4*>(&af[0]) =
                    *reinterpret_cast<const float4*>(&As[bsel][k][ty*4]);
                {
                    const u64* bp = reinterpret_cast<const u64*>(&Bs[bsel][k][tx*4]);
                    bf2[0] = bp[0]; bf2[1] = bp[1];
                }
                {
                    const u64* bp = reinterpret_cast<const u64*>(&Bs[bsel][k][64 + tx*4]);
                    bf2[2] = bp[0]; bf2[3] = bp[1];
                }
                #pragma unroll
                for (int i = 0; i < TM; i++) {
                    u64 a2 = pack2(af[i]);
                    #pragma unroll
                    for (int j = 0; j < TN/2; j++)
                        fma2(accp[i][j], a2, bf2[j]);
                }
            }
        };
        __syncthreads();
        ldg(0); sts(0);
        __syncthreads();
        int buf = 0;
        for (int k0 = BK; k0 < K; k0 += BK) {
            ldg(k0);
            compute(buf);
            sts(buf ^ 1);
            __syncthreads();
            buf ^= 1;
        }
        compute(buf);
    };

    run(A1, B1, K1, accA, fuse != 0);
    run(A2, B2, K2, accB, false);

    float (*Bs2)[BK][64] = reinterpret_cast<float (*)[BK][64]>(&As[0][0][0]);
    const int ty2 = tid >> 4;
    const int tx2 = tid & 15;
    u64 acc3[4][2];
    #pragma unroll
    for (int i = 0; i < 4; i++) { acc3[i][0] = 0ull; acc3[i][1] = 0ull; }

    #pragma unroll
    for (int half = 0; half < 2; half++) {
        __syncthreads();
        #pragma unroll
        for (int i = 0; i < TM; i++) {
            float2 pa0 = unpack2(accA[i][half*2+0]);
            float2 pa1 = unpack2(accA[i][half*2+1]);
            float2 pb0 = unpack2(accB[i][half*2+0]);
            float2 pb1 = unpack2(accB[i][half*2+1]);
            int mloc = ty*4 + i;
            Ps[tx*4+0][mloc] = siluf(pa0.x) * pb0.x;
            Ps[tx*4+1][mloc] = siluf(pa0.y) * pb0.y;
            Ps[tx*4+2][mloc] = siluf(pa1.x) * pb1.x;
            Ps[tx*4+3][mloc] = siluf(pa1.y) * pb1.y;
        }
        float4 rw;
        auto ldgW = [&](int kt) {
            rw = *reinterpret_cast<const float4*>(
                &Wd[(size_t)(half*64 + kt + (tid >> 4))*DT_ + (tid & 15)*4]);
        };
        auto stsW = [&](int bsel) {
            *reinterpret_cast<float4*>(&Bs2[bsel][tid >> 4][(tid & 15)*4]) = rw;
        };
        auto computeW = [&](int bsel, int kt) {
            #pragma unroll
            for (int k = 0; k < BK; k++) {
                float af[4];
                #pragma unroll
                for (int i = 0; i < 4; i++)
                    af[i] = Ps[kt + k][ty2*4 + i];
                u64 bf2[2];
                const u64* bp = reinterpret_cast<const u64*>(&Bs2[bsel][k][tx2*4]);
                bf2[0] = bp[0]; bf2[1] = bp[1];
                #pragma unroll
                for (int i = 0; i < 4; i++) {
                    u64 a2 = pack2(af[i]);
                    fma2(acc3[i][0], a2, bf2[0]);
                    fma2(acc3[i][1], a2, bf2[1]);
                }
            }
        };
        ldgW(0);
        __syncthreads();
        stsW(0);
        __syncthreads();
        int buf = 0;
        #pragma unroll
        for (int kt = BK; kt < 64; kt += BK) {
            ldgW(kt);
            computeW(buf, kt - BK);
            stsW(buf ^ 1);
            __syncthreads();
            buf ^= 1;
        }
        computeW(buf, 64 - BK);
    }

    #pragma unroll
    for (int i = 0; i < 4; i++) {
        size_t r = (size_t)(row0 + ty2*4 + i);
        float2 p0 = unpack2(acc3[i][0]);
        float2 p1 = unpack2(acc3[i][1]);
        float4 v = make_float4(p0.x, p0.y, p1.x, p1.y);
        *reinterpret_cast<float4*>(&X[r*DT_ + tx2*4]) = v;
    }
}

// ================= fused: m += silu(segE@Wup); aN-scatter of silu(m@Wa)*(rbf@Wr2) ======
// Dynamic smem: Ms[64][132] | As[2][16][68] | Bs[2][16][128]  (Bs2 overlays Bs)
#define DS_SMEM ((64*132 + 2*16*68 + 2*16*128) * 4)
__global__ void __launch_bounds__(256)
dual_scat_k(const float* __restrict__ segE, const float* __restrict__ Wup,
            float* __restrict__ gm,
            const float* __restrict__ B1,      // Wa [128x128]
            const float* __restrict__ A2,      // rbf [E x 64]
            const float* __restrict__ B2,      // Wr2 [64x128]
            float* __restrict__ C, const int* __restrict__ dstIdx)
{
    extern __shared__ float sm[];
    float (*Ms)[132]      = reinterpret_cast<float(*)[132]>(sm);
    float (*As)[16][68]   = reinterpret_cast<float(*)[16][68]>(sm + 64*132);
    float (*Bs)[16][128]  = reinterpret_cast<float(*)[16][128]>(sm + 64*132 + 2*16*68);
    float (*Bs2)[16][64]  = reinterpret_cast<float(*)[16][64]>(sm + 64*132 + 2*16*68);

    const int tid  = threadIdx.x;
    const int tx   = tid & 15;
    const int ty   = tid >> 4;
    const int row0 = blockIdx.x * 64;

    // ---- phase 0: m_new = m + silu(segE @ Wup), two 64-col halves ----
    #pragma unroll
    for (int h = 0; h < 2; h++) {
        u64 acc3[4][2];
        #pragma unroll
        for (int i = 0; i < 4; i++) { acc3[i][0] = 0ull; acc3[i][1] = 0ull; }
        float4 ra, rbw;
        auto ldg0 = [&](int k0) {
            ra  = *reinterpret_cast<const float4*>(
                &segE[(size_t)(row0 + (tid >> 2))*DT_ + k0 + (tid & 3)*4]);
            rbw = *reinterpret_cast<const float4*>(
                &Wup[(size_t)(k0 + (tid >> 4))*EE_ + h*64 + (tid & 15)*4]);
        };
        auto sts0 = [&](int bsel) {
            int r = tid >> 2, kq = (tid & 3)*4;
            As[bsel][kq+0][r] = ra.x;
            As[bsel][kq+1][r] = ra.y;
            As[bsel][kq+2][r] = ra.z;
            As[bsel][kq+3][r] = ra.w;
            *reinterpret_cast<float4*>(&Bs2[bsel][tid >> 4][(tid & 15)*4]) = rbw;
        };
        auto comp0 = [&](int bsel) {
            #pragma unroll
            for (int k = 0; k < 16; k++) {
                float af[4];
                *reinterpret_cast<float4*>(&af[0]) =
                    *reinterpret_cast<const float4*>(&As[bsel][k][ty*4]);
                u64 bf2[2];
                const u64* bp = reinterpret_cast<const u64*>(&Bs2[bsel][k][tx*4]);
                bf2[0] = bp[0]; bf2[1] = bp[1];
                #pragma unroll
                for (int i = 0; i < 4; i++) {
                    u64 a2 = pack2(af[i]);
                    fma2(acc3[i][0], a2, bf2[0]);
                    fma2(acc3[i][1], a2, bf2[1]);
                }
            }
        };
        __syncthreads();
        ldg0(0); sts0(0);
        __syncthreads();
        int buf = 0;
        #pragma unroll
        for (int k0 = 16; k0 < DT_; k0 += 16) {
            ldg0(k0);
            comp0(buf);
            sts0(buf ^ 1);
            __syncthreads();
            buf ^= 1;
        }
        comp0(buf);
        // epilogue: m_new = m_old + silu(acc3) -> g_m and Ms
        #pragma unroll
        for (int i = 0; i < 4; i++) {
            int rl = ty*4 + i;
            size_t go = (size_t)(row0 + rl)*EE_ + h*64 + tx*4;
            float4 mo = *reinterpret_cast<const float4*>(&gm[go]);
            float2 p0 = unpack2(acc3[i][0]);
            float2 p1 = unpack2(acc3[i][1]);
            float4 mn;
            mn.x = mo.x + siluf(p0.x);
            mn.y = mo.y + siluf(p0.y);
            mn.z = mo.z + siluf(p1.x);
            mn.w = mo.w + siluf(p1.y);
            *reinterpret_cast<float4*>(&gm[go]) = mn;
            *reinterpret_cast<float4*>(&Ms[rl][h*64 + tx*4]) = mn;
        }
    }
    __syncthreads();   // Ms complete; Bs2 free

    u64 accA[4][4], accB[4][4];
    #pragma unroll
    for (int i = 0; i < 4; i++)
        #pragma unroll
        for (int j = 0; j < 4; j++) { accA[i][j] = 0ull; accB[i][j] = 0ull; }

    // ---- pass 1: m_new @ Wa (K=128), A from Ms ----
    {
        float4 rb0, rb1;
        auto ldg1 = [&](int k0) {
            rb0 = *reinterpret_cast<const float4*>(
                &B1[(size_t)(k0 + (tid >> 5))*EE_ + (tid & 31)*4]);
            rb1 = *reinterpret_cast<const float4*>(
                &B1[(size_t)(k0 + 8 + (tid >> 5))*EE_ + (tid & 31)*4]);
        };
        auto sts1 = [&](int bsel) {
            *reinterpret_cast<float4*>(&Bs[bsel][tid >> 5][(tid & 31)*4]) = rb0;
            *reinterpret_cast<float4*>(&Bs[bsel][8 + (tid >> 5)][(tid & 31)*4]) = rb1;
        };
        auto comp1 = [&](int bsel, int kb) {
            #pragma unroll
            for (int k = 0; k < 16; k++) {
                float af[4];
                #pragma unroll
                for (int i = 0; i < 4; i++)
                    af[i] = Ms[ty*4 + i][kb + k];
                u64 bf2[4];
                {
                    const u64* bp = reinterpret_cast<const u64*>(&Bs[bsel][k][tx*4]);
                    bf2[0] = bp[0]; bf2[1] = bp[1];
                }
                {
                    const u64* bp = reinterpret_cast<const u64*>(&Bs[bsel][k][64 + tx*4]);
                    bf2[2] = bp[0]; bf2[3] = bp[1];
                }
                #pragma unroll
                for (int i = 0; i < 4; i++) {
                    u64 a2 = pack2(af[i]);
                    #pragma unroll
                    for (int j = 0; j < 4; j++)
                        fma2(accA[i][j], a2, bf2[j]);
                }
            }
        };
        ldg1(0); sts1(0);
        __syncthreads();
        int buf = 0;
        #pragma unroll
        for (int k0 = 16; k0 < EE_; k0 += 16) {
            ldg1(k0);
            comp1(buf, k0 - 16);
            sts1(buf ^ 1);
            __syncthreads();
            buf ^= 1;
        }
        comp1(buf, EE_ - 16);
    }

    // ---- pass 2: rbf @ Wr2 (K=64), standard staging ----
    {
        float4 ra, rb0, rb1;
        auto ldg2 = [&](int k0) {
            ra  = *reinterpret_cast<const float4*>(
                &A2[(size_t)(row0 + (tid >> 2))*NR_ + k0 + (tid & 3)*4]);
            rb0 = *reinterpret_cast<const float4*>(
                &B2[(size_t)(k0 + (tid >> 5))*EE_ + (tid & 31)*4]);
            rb1 = *reinterpret_cast<const float4*>(
                &B2[(size_t)(k0 + 8 + (tid >> 5))*EE_ + (tid & 31)*4]);
        };
        auto sts2 = [&](int bsel) {
            int r = tid >> 2, kq = (tid & 3)*4;
            As[bsel][kq+0][r] = ra.x;
            As[bsel][kq+1][r] = ra.y;
            As[bsel][kq+2][r] = ra.z;
            As[bsel][kq+3][r] = ra.w;
            *reinterpret_cast<float4*>(&Bs[bsel][tid >> 5][(tid & 31)*4]) = rb0;
            *reinterpret_cast<float4*>(&Bs[bsel][8 + (tid >> 5)][(tid & 31)*4]) = rb1;
        };
        auto comp2 = [&](int bsel) {
            #pragma unroll
            for (int k = 0; k < 16; k++) {
                float af[4];
                *reinterpret_cast<float4*>(&af[0]) =
                    *reinterpret_cast<const float4*>(&As[bsel][k][ty*4]);
                u64 bf2[4];
                {
                    const u64* bp = reinterpret_cast<const u64*>(&Bs[bsel][k][tx*4]);
                    bf2[0] = bp[0]; bf2[1] = bp[1];
                }
                {
                    const u64* bp = reinterpret_cast<const u64*>(&Bs[bsel][k][64 + tx*4]);
                    bf2[2] = bp[0]; bf2[3] = bp[1];
                }
                #pragma unroll
                for (int i = 0; i < 4; i++) {
                    u64 a2 = pack2(af[i]);
                    #pragma unroll
                    for (int j = 0; j < 4; j++)
                        fma2(accB[i][j], a2, bf2[j]);
                }
            }
        };
        __syncthreads();
        ldg2(0); sts2(0);
        __syncthreads();
        int buf = 0;
        #pragma unroll
        for (int k0 = 16; k0 < NR_; k0 += 16) {
            ldg2(k0);
            comp2(buf);
            sts2(buf ^ 1);
            __syncthreads();
            buf ^= 1;
        }
        comp2(buf);
    }

    // ---- scatter: aN[dst] += silu(accA) * accB (red.v4) ----
    #pragma unroll
    for (int i = 0; i < 4; i++) {
        int r = row0 + ty*4 + i;
        int dr = dstIdx[r];
        float2 pa0 = unpack2(accA[i][0]), pb0 = unpack2(accB[i][0]);
        float2 pa1 = unpack2(accA[i][1]), pb1 = unpack2(accB[i][1]);
        float4 v0 = make_float4(siluf(pa0.x)*pb0.x, siluf(pa0.y)*pb0.y,
                                siluf(pa1.x)*pb1.x, siluf(pa1.y)*pb1.y);
        red4(&C[(size_t)dr*128 + tx*4], v0);
        float2 pa2 = unpack2(accA[i][2]), pb2 = unpack2(accB[i][2]);
        float2 pa3 = unpack2(accA[i][3]), pb3 = unpack2(accB[i][3]);
        float4 v1 = make_float4(siluf(pa2.x)*pb2.x, siluf(pa2.y)*pb2.y,
                                siluf(pa3.x)*pb3.x, siluf(pa3.y)*pb3.y);
        red4(&C[(size_t)dr*128 + 64 + tx*4], v1);
    }
}

// ---------------- launch ----------------
extern "C" void kernel_launch(void* const* d_in, const int* in_sizes, int n_in,
                              void* d_out, int out_size)
{
    const float* noise   = (const float*)d_in[0];
    const float* frac    = (const float*)d_in[1];
    const float* lengths = (const float*)d_in[2];
    const float* angles  = (const float*)d_in[3];
    const int*   atype   = (const int*)  d_in[4];
    const int*   natoms  = (const int*)  d_in[5];
    const int*   ei      = (const int*)  d_in[6];
    const int*   ji      = (const int*)  d_in[7];
    const int*   kj      = (const int*)  d_in[8];
    const float* emb     = (const float*)d_in[9];
    const float* W_hz    = (const float*)d_in[10];
    const float* W_edge  = (const float*)d_in[11];
    const float* Wm      = (const float*)d_in[12];
    const float* Wr1     = (const float*)d_in[13];
    const float* Wdown   = (const float*)d_in[14];
    const float* Wcbf    = (const float*)d_in[15];
    const float* Wup     = (const float*)d_in[16];
    const float* Wa      = (const float*)d_in[17];
    const float* Wr2     = (const float*)d_in[18];
    const float* Wh      = (const float*)d_in[19];
    const float* Ws      = (const float*)d_in[20];
    const float* Wt      = (const float*)d_in[21];
    const float* W_out   = (const float*)d_in[22];
    const float* W_fc0   = (const float*)d_in[23];
    const float* b_fc0   = (const float*)d_in[24];
    const float* W_fc1   = (const float*)d_in[25];
    const float* b_fc1   = (const float*)d_in[26];
    const float* W_fc2   = (const float*)d_in[27];
    const float* b_fc2   = (const float*)d_in[28];
    float* out = (float*)d_out;

    float *p_h, *p_X1, *p_X2, *p_m, *p_x, *p_segE, *p_aN,
          *p_hs, *p_ht, *p_rbf, *p_z, *p_f0, *p_f1;
    cudaGetSymbolAddress((void**)&p_h,    g_h);
    cudaGetSymbolAddress((void**)&p_X1,   g_X1);
    cudaGetSymbolAddress((void**)&p_X2,   g_X2);
    cudaGetSymbolAddress((void**)&p_m,    g_m);
    cudaGetSymbolAddress((void**)&p_x,    g_x);
    cudaGetSymbolAddress((void**)&p_segE, g_segE);
    cudaGetSymbolAddress((void**)&p_aN,   g_aN);
    cudaGetSymbolAddress((void**)&p_hs,   g_hs);
    cudaGetSymbolAddress((void**)&p_ht,   g_ht);
    cudaGetSymbolAddress((void**)&p_rbf,  g_rbf);
    cudaGetSymbolAddress((void**)&p_z,    g_z);
    cudaGetSymbolAddress((void**)&p_f0,   g_f0);
    cudaGetSymbolAddress((void**)&p_f1,   g_f1);

    cudaFuncSetAttribute(dual_scat_k,
                         cudaFuncAttributeMaxDynamicSharedMemorySize, DS_SMEM);

    // ---- geometry ----
    k_pos<<<(N_ + 255)/256, 256>>>(frac, lengths, angles);
    k_edge<<<E_/256, 256>>>(ei);
    k_cth<<<T_/256, 256>>>(ji, kj);
    k_h<<<N_, EA_>>>(atype, noise, emb, W_hz);

    // ---- m init ----
    gemm32_k<0><<<dim3(N_/32, 2), 256>>>(p_h, W_edge, W_edge + 128*EE_,
                                         p_X1, p_X2, EA_);
    gemm_k<<<E_/128, 256>>>(p_rbf, W_edge + 256*EE_, p_m, NR_, ei);

    for (int b = 0; b < NB_; b++) {
        const float* Wm_b    = Wm    + (size_t)b*EE_*EE_;
        const float* Wr1_b   = Wr1   + (size_t)b*NR_*EE_;
        const float* Wdown_b = Wdown + (size_t)b*EE_*DT_;
        const float* Wcbf_b  = Wcbf  + (size_t)b*NS_*DT_;
        const float* Wup_b   = Wup   + (size_t)b*DT_*EE_;
        const float* Wa_b    = Wa    + (size_t)b*EE_*EA_;
        const float* Wr2_b   = Wr2   + (size_t)b*NR_*EA_;
        const float* Wh_b    = Wh    + (size_t)b*EA_*EA_;
        const float* Ws_b    = Ws    + (size_t)b*EA_*EE_;
        const float* Wt_b    = Wt    + (size_t)b*EA_*EE_;

        // x = (silu(m'@Wm) * (rbf@Wr1)) @ Wdown;  m' applies prev iter's edge update
        dual_down_k<<<E_/64, 256>>>(p_m, Wm_b, p_rbf, Wr1_b, Wdown_b, p_x,
                                    ei, (b > 0) ? 1 : 0);

        // triplet aggregation (red.v4 scatter)
        k_zero4<<<(E_*DT_/4 + 255)/256, 256>>>((float4*)p_segE, E_*DT_/4);
        k_triplet<<<T_/32, 256>>>(ji, kj, Wcbf_b);

        // fused: m += silu(segE@Wup); aN = scatter_dst(silu(m@Wa) * (rbf@Wr2))
        k_zero4<<<(N_*EA_/4 + 255)/256, 256>>>((float4*)p_aN, N_*EA_/4);
        dual_scat_k<<<E_/64, 256, DS_SMEM>>>(p_segE, Wup_b, p_m,
                                             Wa_b, p_rbf, Wr2_b, p_aN, ei + E_);

        // h += silu(aN @ Wh)
        gemm32_k<2><<<dim3(N_/32, 1), 256>>>(p_aN, Wh_b, Wh_b, p_h, p_h, EA_);

        // hs/ht for next iter's fused edge update (dead after the final block)
        if (b < NB_ - 1) {
            gemm32_k<0><<<dim3(N_/32, 2), 256>>>(p_h, Ws_b, Wt_b, p_hs, p_ht, EA_);
        }
    }

    // ---- readout ----
    gemm32_k<0><<<dim3(N_/32, 1), 256>>>(p_h, W_out, W_out, p_X1, p_X1, EA_);
    k_pool<<<B_, LAT_>>>(natoms);

    k_fc<LAT_, HID_, true ><<<B_, 256>>>(p_z,  W_fc0, b_fc0, p_f0);
    k_fc<HID_, HID_, true ><<<B_, 256>>>(p_f0, W_fc1, b_fc1, p_f1);
    k_fc<HID_, NC_,  false><<<B_, 256>>>(p_f1, W_fc2, b_fc2, out);
}